// round 14
// baseline (speedup 1.0000x reference)
#include <cuda_runtime.h>
#include <cuda_bf16.h>
#include <cstdint>

#define NPIX 65536

// ---------------------------------------------------------------------------
// Device-global scratch (no runtime allocation allowed)
// ---------------------------------------------------------------------------
__device__ __nv_bfloat16 g_x_hi[512u * 65536u];   // [pix][512]
__device__ __nv_bfloat16 g_x_lo[512u * 65536u];
__device__ float         g_qkv[1536u * 65536u];   // [e][pix] fp32
__device__ __nv_bfloat16 g_ao_hi[512u * 65536u];  // [pix][512]
__device__ __nv_bfloat16 g_ao_lo[512u * 65536u];
__device__ __nv_bfloat16 g_wq_hi[1536u * 512u];   // [e][d]
__device__ __nv_bfloat16 g_wq_lo[1536u * 512u];
__device__ __nv_bfloat16 g_wo_hi[512u * 512u];
__device__ __nv_bfloat16 g_wo_lo[512u * 512u];

// ---------------------------------------------------------------------------
// PTX helpers
// ---------------------------------------------------------------------------
__device__ __forceinline__ uint32_t smem_u32(const void* p) {
  uint32_t a;
  asm("{ .reg .u64 t; cvta.to.shared.u64 t, %1; cvt.u32.u64 %0, t; }"
      : "=r"(a) : "l"(p));
  return a;
}
__device__ __forceinline__ void cpa16(uint32_t dst, const void* src) {
  asm volatile("cp.async.cg.shared.global [%0], [%1], 16;" :: "r"(dst), "l"(src));
}
__device__ __forceinline__ void ldsm4(uint32_t* r, uint32_t addr) {
  asm volatile("ldmatrix.sync.aligned.m8n8.x4.shared.b16 {%0,%1,%2,%3}, [%4];"
               : "=r"(r[0]), "=r"(r[1]), "=r"(r[2]), "=r"(r[3]) : "r"(addr));
}
__device__ __forceinline__ void mma_bf16(float* c, const uint32_t* a,
                                         const uint32_t* b) {
  asm volatile(
      "mma.sync.aligned.m16n8k16.row.col.f32.bf16.bf16.f32 "
      "{%0,%1,%2,%3}, {%4,%5,%6,%7}, {%8,%9}, {%0,%1,%2,%3};"
      : "+f"(c[0]), "+f"(c[1]), "+f"(c[2]), "+f"(c[3])
      : "r"(a[0]), "r"(a[1]), "r"(a[2]), "r"(a[3]), "r"(b[0]), "r"(b[1]));
}

// packed fp32x2 math
__device__ __forceinline__ unsigned long long pack2(float a) {
  unsigned long long r;
  asm("mov.b64 %0, {%1, %1};" : "=l"(r) : "r"(__float_as_uint(a)));
  return r;
}
__device__ __forceinline__ void fma2(unsigned long long& d,
                                     unsigned long long a, unsigned long long b) {
  asm("fma.rn.f32x2 %0, %1, %2, %0;" : "+l"(d) : "l"(a), "l"(b));
}
__device__ __forceinline__ float lo32(unsigned long long v) {
  return __uint_as_float((unsigned)v);
}
__device__ __forceinline__ float hi32(unsigned long long v) {
  return __uint_as_float((unsigned)(v >> 32));
}

__device__ __forceinline__ void split2(float a, float b, uint32_t& hi, uint32_t& lo) {
  __nv_bfloat16 ha = __float2bfloat16_rn(a);
  __nv_bfloat16 hb = __float2bfloat16_rn(b);
  float ra = a - __bfloat162float(ha);
  float rb = b - __bfloat162float(hb);
  __nv_bfloat162 th; th.x = ha; th.y = hb;
  __nv_bfloat162 tl; tl.x = __float2bfloat16_rn(ra); tl.y = __float2bfloat16_rn(rb);
  hi = *(uint32_t*)&th;
  lo = *(uint32_t*)&tl;
}

// ---------------------------------------------------------------------------
// Weight split kernel
// ---------------------------------------------------------------------------
__global__ __launch_bounds__(256) void split_kernel(
    const float* __restrict__ src, __nv_bfloat16* __restrict__ hi,
    __nv_bfloat16* __restrict__ lo, int n4) {
  int i = blockIdx.x * 256 + threadIdx.x;
  if (i >= n4) return;
  float4 v = ((const float4*)src)[i];
  uint32_t h0, l0, h1, l1;
  split2(v.x, v.y, h0, l0);
  split2(v.z, v.w, h1, l1);
  ((uint2*)hi)[i] = make_uint2(h0, h1);
  ((uint2*)lo)[i] = make_uint2(l0, l1);
}

// ---------------------------------------------------------------------------
// Kernel 1: channel LayerNorm + roll(-4,-4) + window partition -> bf16 hi/lo
// ---------------------------------------------------------------------------
__global__ __launch_bounds__(128) void ln_kernel(
    const float* __restrict__ x, const float* __restrict__ gamma,
    const float* __restrict__ beta) {
  __shared__ float gs[512], bs[512];
  for (int i = threadIdx.x; i < 512; i += 128) {
    gs[i] = gamma[i];
    bs[i] = beta[i];
  }
  __syncthreads();

  int b = blockIdx.x >> 7;
  int h = blockIdx.x & 127;
  int w = threadIdx.x;
  const float* p = x + (((size_t)b * 512) * 128 + h) * 128 + w;

  float s = 0.f, sq = 0.f;
#pragma unroll 8
  for (int d = 0; d < 512; d++) {
    float v = p[(size_t)d * 16384];
    s += v;
    sq = fmaf(v, v, sq);
  }
  float mean = s * (1.f / 512.f);
  float var = sq * (1.f / 512.f) - mean * mean;
  float rstd = rsqrtf(var + 1e-5f);

  int hp = (h + 124) & 127;
  int wp = (w + 124) & 127;
  int pix = ((((b << 4) + (hp >> 3)) << 4) + (wp >> 3)) * 64 + ((hp & 7) << 3) + (wp & 7);

  __nv_bfloat16* hrow = g_x_hi + (size_t)pix * 512;
  __nv_bfloat16* lrow = g_x_lo + (size_t)pix * 512;
#pragma unroll 2
  for (int d0 = 0; d0 < 512; d0 += 8) {
    uint32_t hw[4], lw[4];
#pragma unroll
    for (int j = 0; j < 4; j++) {
      int d = d0 + 2 * j;
      float v0 = (p[(size_t)d * 16384] - mean) * rstd * gs[d] + bs[d];
      float v1 = (p[(size_t)(d + 1) * 16384] - mean) * rstd * gs[d + 1] + bs[d + 1];
      split2(v0, v1, hw[j], lw[j]);
    }
    *(uint4*)(hrow + d0) = make_uint4(hw[0], hw[1], hw[2], hw[3]);
    *(uint4*)(lrow + d0) = make_uint4(lw[0], lw[1], lw[2], lw[3]);
  }
}

// ---------------------------------------------------------------------------
// mma.sync bf16 split-precision GEMM: CTA 128x128, 4 warps (2m x 2n),
// warp tile 64x64, BK=32, 2-stage cp.async (R6 rhythm), 128 threads.
// Stage: AH(10240) AL(10240) BH(10240) BL(10240) = 40960 B; 2 stages, row 80 B.
// Halves ldmatrix traffic per FLOP vs 64x32 warp tile while keeping 2 CTAs/SM.
// ---------------------------------------------------------------------------
#define STAGE_BYTES 40960
#define SMEM_BYTES (2 * STAGE_BYTES)

__device__ __forceinline__ void stage_load(
    const __nv_bfloat16* __restrict__ Ahi, const __nv_bfloat16* __restrict__ Alo,
    const __nv_bfloat16* __restrict__ Bhi, const __nv_bfloat16* __restrict__ Blo,
    int m0, int n0, int k0, uint32_t sstage, int tid) {
#pragma unroll
  for (int i = 0; i < 4; i++) {
    int g = i * 128 + tid;           // 0..511 (128 rows x 4 chunks)
    int row = g >> 2, c = g & 3;
    uint32_t off = (uint32_t)row * 80 + c * 16;
    size_t asrc = (size_t)(m0 + row) * 512 + k0 + c * 8;
    size_t bsrc = (size_t)(n0 + row) * 512 + k0 + c * 8;
    cpa16(sstage + off,         Ahi + asrc);
    cpa16(sstage + 10240 + off, Alo + asrc);
    cpa16(sstage + 20480 + off, Bhi + bsrc);
    cpa16(sstage + 30720 + off, Blo + bsrc);
  }
  asm volatile("cp.async.commit_group;");
}

template <bool FINAL>
__global__ __launch_bounds__(128, 2) void mma_gemm(
    const __nv_bfloat16* __restrict__ Ahi, const __nv_bfloat16* __restrict__ Alo,
    const __nv_bfloat16* __restrict__ Bhi, const __nv_bfloat16* __restrict__ Blo,
    const float* __restrict__ bias, float* __restrict__ outp) {
  extern __shared__ __align__(128) char smem[];
  const int tid = threadIdx.x;
  const int lane = tid & 31;
  const int warp = tid >> 5;
  const int wm = warp & 1;      // 0..1 (64 m each)
  const int wn = warp >> 1;     // 0..1 (64 n each)
  const int m0 = blockIdx.x << 7;  // m fastest -> weights stay L2-resident
  const int n0 = blockIdx.y << 7;
  const uint32_t sb = smem_u32(smem);

  const int arow = (lane & 7) + ((lane >> 3) & 1) * 8;
  const uint32_t aoff = (uint32_t)(wm * 64 + arow) * 80 + (lane >> 4) * 16;
  const int brow = (lane & 7) + (lane >> 4) * 8;
  const uint32_t bksel = ((lane >> 3) & 1) * 16;

  float acc[4][8][4];
#pragma unroll
  for (int mi = 0; mi < 4; mi++)
#pragma unroll
    for (int ni = 0; ni < 8; ni++)
#pragma unroll
      for (int r = 0; r < 4; r++) acc[mi][ni][r] = 0.f;

  stage_load(Ahi, Alo, Bhi, Blo, m0, n0, 0, sb, tid);

  for (int kc = 0; kc < 16; kc++) {
    const uint32_t cur = sb + (kc & 1) * STAGE_BYTES;
    if (kc < 15) {
      stage_load(Ahi, Alo, Bhi, Blo, m0, n0, (kc + 1) * 32,
                 sb + ((kc + 1) & 1) * STAGE_BYTES, tid);
      asm volatile("cp.async.wait_group 1;" ::: "memory");
    } else {
      asm volatile("cp.async.wait_group 0;" ::: "memory");
    }
    __syncthreads();

#pragma unroll
    for (int ks = 0; ks < 2; ks++) {
      uint32_t a_hi[4][4], a_lo[4][4];
#pragma unroll
      for (int mi = 0; mi < 4; mi++) {
        uint32_t ad = cur + aoff + (uint32_t)mi * (16 * 80) + ks * 32;
        ldsm4(a_hi[mi], ad);
        ldsm4(a_lo[mi], ad + 10240);
      }
      uint32_t b_hi[8][2], b_lo[8][2];
#pragma unroll
      for (int nj = 0; nj < 4; nj++) {
        uint32_t bd = cur + 20480 +
                      (uint32_t)(wn * 64 + nj * 16 + brow) * 80 + bksel + ks * 32;
        uint32_t t[4];
        ldsm4(t, bd);
        b_hi[2 * nj][0] = t[0]; b_hi[2 * nj][1] = t[1];
        b_hi[2 * nj + 1][0] = t[2]; b_hi[2 * nj + 1][1] = t[3];
        ldsm4(t, bd + 10240);
        b_lo[2 * nj][0] = t[0]; b_lo[2 * nj][1] = t[1];
        b_lo[2 * nj + 1][0] = t[2]; b_lo[2 * nj + 1][1] = t[3];
      }
#pragma unroll
      for (int mi = 0; mi < 4; mi++) {
#pragma unroll
        for (int ni = 0; ni < 8; ni++) {
          mma_bf16(acc[mi][ni], a_hi[mi], b_hi[ni]);
          mma_bf16(acc[mi][ni], a_hi[mi], b_lo[ni]);
          mma_bf16(acc[mi][ni], a_lo[mi], b_hi[ni]);
        }
      }
    }
    __syncthreads();
  }

  const int g = lane >> 2;
  const int t2 = (lane & 3) * 2;
  if (!FINAL) {
#pragma unroll
    for (int mi = 0; mi < 4; mi++) {
#pragma unroll
      for (int half = 0; half < 2; half++) {
        int e = m0 + wm * 64 + mi * 16 + g + half * 8;
        float* rowp = g_qkv + (size_t)e * NPIX;
#pragma unroll
        for (int ni = 0; ni < 8; ni++) {
          int pix = n0 + wn * 64 + ni * 8 + t2;
          float2 v;
          v.x = acc[mi][ni][2 * half + 0];
          v.y = acc[mi][ni][2 * half + 1];
          *(float2*)(rowp + pix) = v;
        }
      }
    }
  } else {
    size_t pbase[8];
#pragma unroll
    for (int ni = 0; ni < 8; ni++) {
      int pix = n0 + wn * 64 + ni * 8 + t2;
      int win = pix >> 6, l = pix & 63;
      int bb = win >> 8, wh = (win >> 4) & 15, ww = win & 15;
      int hh = ((wh << 3) + (l >> 3) + 4) & 127;
      int wcol = ((ww << 3) + (l & 7) + 4) & 127;
      pbase[ni] = (size_t)bb * 8388608 + (size_t)hh * 128 + wcol;
    }
#pragma unroll
    for (int mi = 0; mi < 4; mi++) {
#pragma unroll
      for (int half = 0; half < 2; half++) {
        int e = m0 + wm * 64 + mi * 16 + g + half * 8;
        float bv = __ldg(bias + e);
#pragma unroll
        for (int ni = 0; ni < 8; ni++) {
          float2 v;
          v.x = acc[mi][ni][2 * half + 0] + bv;
          v.y = acc[mi][ni][2 * half + 1] + bv;
          *(float2*)(outp + pbase[ni] + (size_t)e * 16384) = v;
        }
      }
    }
  }
}

// ---------------------------------------------------------------------------
// Kernel 3: per-(window, head) attention with RoPE, fp32 math via fma.rn.f32x2
// grid = 16384, block 256. thread = (i = tid&63 query row, g = tid>>6 quarter)
// ---------------------------------------------------------------------------
__global__ __launch_bounds__(256) void attn_kernel() {
  __shared__ float qs[64][36];
  __shared__ float ks[64][36];
  __shared__ float vs[64][32];
  __shared__ float lg[64][65];
  __shared__ float redm[64][4];
  __shared__ float reds[64][4];

  int tid = threadIdx.x;
  int win = blockIdx.x >> 4;
  int head = blockIdx.x & 15;
  const float* base = g_qkv + (size_t)(head * 32) * NPIX + (size_t)win * 64;

  {
    int dd = tid >> 3;
    int l0 = (tid & 7) << 3;
    const float* pq = base + (size_t)dd * NPIX + l0;
    const float* pk = pq + (size_t)512 * NPIX;
    const float* pv = pq + (size_t)1024 * NPIX;
    float4 u0 = *(const float4*)pq;
    float4 u1 = *(const float4*)(pq + 4);
    qs[l0 + 0][dd] = u0.x; qs[l0 + 1][dd] = u0.y;
    qs[l0 + 2][dd] = u0.z; qs[l0 + 3][dd] = u0.w;
    qs[l0 + 4][dd] = u1.x; qs[l0 + 5][dd] = u1.y;
    qs[l0 + 6][dd] = u1.z; qs[l0 + 7][dd] = u1.w;
    u0 = *(const float4*)pk;
    u1 = *(const float4*)(pk + 4);
    ks[l0 + 0][dd] = u0.x; ks[l0 + 1][dd] = u0.y;
    ks[l0 + 2][dd] = u0.z; ks[l0 + 3][dd] = u0.w;
    ks[l0 + 4][dd] = u1.x; ks[l0 + 5][dd] = u1.y;
    ks[l0 + 6][dd] = u1.z; ks[l0 + 7][dd] = u1.w;
    u0 = *(const float4*)pv;
    u1 = *(const float4*)(pv + 4);
    vs[l0 + 0][dd] = u0.x; vs[l0 + 1][dd] = u0.y;
    vs[l0 + 2][dd] = u0.z; vs[l0 + 3][dd] = u0.w;
    vs[l0 + 4][dd] = u1.x; vs[l0 + 5][dd] = u1.y;
    vs[l0 + 6][dd] = u1.z; vs[l0 + 7][dd] = u1.w;
  }
  __syncthreads();

#pragma unroll
  for (int it = 0; it < 4; it++) {
    int p = tid + it * 256;
    int l = p >> 4;
    int j = p & 15;
    int pos = (j < 8) ? (l >> 3) : (l & 7);
    int fj = j & 7;
    float freq = expf(-(float)fj * (9.210340371976184f / 8.0f));
    float th = (float)pos * freq;
    float c = cosf(th), s = sinf(th);
    float q0 = qs[l][j], q1 = qs[l][j + 16];
    qs[l][j] = q0 * c - q1 * s;
    qs[l][j + 16] = fmaf(q1, c, q0 * s);
    float k0 = ks[l][j], k1 = ks[l][j + 16];
    ks[l][j] = k0 * c - k1 * s;
    ks[l][j + 16] = fmaf(k1, c, k0 * s);
  }
  __syncthreads();

  int i = tid & 63;
  int g = tid >> 6;

  // q row cached as packed f32x2 (rows are 144 B => 8 B aligned)
  unsigned long long qp[16];
  {
    const unsigned long long* qrow = (const unsigned long long*)&qs[i][0];
#pragma unroll
    for (int d2 = 0; d2 < 16; d2++) qp[d2] = qrow[d2];
  }

  // logits for j in [g*16, g*16+16) with FFMA2
#pragma unroll
  for (int jj = 0; jj < 16; jj++) {
    int j = (g << 4) + jj;
    const unsigned long long* krow = (const unsigned long long*)&ks[j][0];
    unsigned long long acc2 = 0ull;
#pragma unroll
    for (int d2 = 0; d2 < 16; d2++) fma2(acc2, qp[d2], krow[d2]);
    lg[i][j] = (lo32(acc2) + hi32(acc2)) * 0.17677669529663687f;
  }
  __syncthreads();

  float mx = -1e30f;
#pragma unroll
  for (int jj = 0; jj < 16; jj++) mx = fmaxf(mx, lg[i][(g << 4) + jj]);
  redm[i][g] = mx;
  __syncthreads();
  mx = fmaxf(fmaxf(redm[i][0], redm[i][1]), fmaxf(redm[i][2], redm[i][3]));
  float sum = 0.f;
#pragma unroll
  for (int jj = 0; jj < 16; jj++) {
    int j = (g << 4) + jj;
    float e = __expf(lg[i][j] - mx);
    lg[i][j] = e;
    sum += e;
  }
  reds[i][g] = sum;
  __syncthreads();
  float inv = 1.0f / (reds[i][0] + reds[i][1] + reds[i][2] + reds[i][3]);

  // P @ V with FFMA2: thread covers dd in [g*8, g*8+8)
  unsigned long long o2[4] = {0ull, 0ull, 0ull, 0ull};
#pragma unroll 4
  for (int j = 0; j < 64; j++) {
    unsigned long long pv2 = pack2(lg[i][j] * inv);
    const unsigned long long* vp = (const unsigned long long*)&vs[j][g << 3];
    fma2(o2[0], pv2, vp[0]);
    fma2(o2[1], pv2, vp[1]);
    fma2(o2[2], pv2, vp[2]);
    fma2(o2[3], pv2, vp[3]);
  }

  size_t row = (size_t)win * 64 + i;
  int col = head * 32 + (g << 3);
  uint32_t hw[4], lw[4];
#pragma unroll
  for (int j = 0; j < 4; j++) split2(lo32(o2[j]), hi32(o2[j]), hw[j], lw[j]);
  *(uint4*)(g_ao_hi + row * 512 + col) = make_uint4(hw[0], hw[1], hw[2], hw[3]);
  *(uint4*)(g_ao_lo + row * 512 + col) = make_uint4(lw[0], lw[1], lw[2], lw[3]);
}

// ---------------------------------------------------------------------------
extern "C" void kernel_launch(void* const* d_in, const int* in_sizes, int n_in,
                              void* d_out, int out_size) {
  const float* x = (const float*)d_in[0];
  const float* ln_g = (const float*)d_in[1];
  const float* ln_b = (const float*)d_in[2];
  const float* w_qkv = (const float*)d_in[3];
  const float* w_out = (const float*)d_in[4];
  const float* b_out = (const float*)d_in[5];
  float* out = (float*)d_out;
  (void)in_sizes; (void)n_in; (void)out_size;

  cudaFuncSetAttribute(mma_gemm<false>, cudaFuncAttributeMaxDynamicSharedMemorySize, SMEM_BYTES);
  cudaFuncSetAttribute(mma_gemm<true>, cudaFuncAttributeMaxDynamicSharedMemorySize, SMEM_BYTES);

  __nv_bfloat16 *p_wq_hi, *p_wq_lo, *p_wo_hi, *p_wo_lo, *p_x_hi, *p_x_lo, *p_ao_hi, *p_ao_lo;
  cudaGetSymbolAddress((void**)&p_wq_hi, g_wq_hi);
  cudaGetSymbolAddress((void**)&p_wq_lo, g_wq_lo);
  cudaGetSymbolAddress((void**)&p_wo_hi, g_wo_hi);
  cudaGetSymbolAddress((void**)&p_wo_lo, g_wo_lo);
  cudaGetSymbolAddress((void**)&p_x_hi, g_x_hi);
  cudaGetSymbolAddress((void**)&p_x_lo, g_x_lo);
  cudaGetSymbolAddress((void**)&p_ao_hi, g_ao_hi);
  cudaGetSymbolAddress((void**)&p_ao_lo, g_ao_lo);

  split_kernel<<<(1536 * 512 / 4 + 255) / 256, 256>>>(w_qkv, p_wq_hi, p_wq_lo, 1536 * 512 / 4);
  split_kernel<<<(512 * 512 / 4 + 255) / 256, 256>>>(w_out, p_wo_hi, p_wo_lo, 512 * 512 / 4);
  ln_kernel<<<512, 128>>>(x, ln_g, ln_b);
  // A = weights (M rows), B = activations (N pix); m fastest keeps weights in L2
  mma_gemm<false><<<dim3(12, 512), 128, SMEM_BYTES>>>(p_wq_hi, p_wq_lo, p_x_hi, p_x_lo, nullptr, nullptr);
  attn_kernel<<<16384, 256>>>();
  mma_gemm<true><<<dim3(4, 512), 128, SMEM_BYTES>>>(p_wo_hi, p_wo_lo, p_ao_hi, p_ao_lo, b_out, out);
}

// round 15
// speedup vs baseline: 1.0016x; 1.0016x over previous
#include <cuda_runtime.h>
#include <cuda_bf16.h>
#include <cstdint>

#define NPIX 65536

// ---------------------------------------------------------------------------
// Device-global scratch (no runtime allocation allowed)
// ---------------------------------------------------------------------------
__device__ __nv_bfloat16 g_x_hi[512u * 65536u];   // [pix][512]
__device__ __nv_bfloat16 g_x_lo[512u * 65536u];
__device__ float         g_qkv[1536u * 65536u];   // [e][pix] fp32
__device__ __nv_bfloat16 g_ao_hi[512u * 65536u];  // [pix][512]
__device__ __nv_bfloat16 g_ao_lo[512u * 65536u];
__device__ __nv_bfloat16 g_wq_hi[1536u * 512u];   // [e][d]
__device__ __nv_bfloat16 g_wq_lo[1536u * 512u];
__device__ __nv_bfloat16 g_wo_hi[512u * 512u];
__device__ __nv_bfloat16 g_wo_lo[512u * 512u];

// ---------------------------------------------------------------------------
// PTX helpers
// ---------------------------------------------------------------------------
__device__ __forceinline__ uint32_t smem_u32(const void* p) {
  uint32_t a;
  asm("{ .reg .u64 t; cvta.to.shared.u64 t, %1; cvt.u32.u64 %0, t; }"
      : "=r"(a) : "l"(p));
  return a;
}
__device__ __forceinline__ void cpa16(uint32_t dst, const void* src) {
  asm volatile("cp.async.cg.shared.global [%0], [%1], 16;" :: "r"(dst), "l"(src));
}
__device__ __forceinline__ void ldsm4(uint32_t* r, uint32_t addr) {
  asm volatile("ldmatrix.sync.aligned.m8n8.x4.shared.b16 {%0,%1,%2,%3}, [%4];"
               : "=r"(r[0]), "=r"(r[1]), "=r"(r[2]), "=r"(r[3]) : "r"(addr));
}
__device__ __forceinline__ void mma_bf16(float* c, const uint32_t* a,
                                         const uint32_t* b) {
  asm volatile(
      "mma.sync.aligned.m16n8k16.row.col.f32.bf16.bf16.f32 "
      "{%0,%1,%2,%3}, {%4,%5,%6,%7}, {%8,%9}, {%0,%1,%2,%3};"
      : "+f"(c[0]), "+f"(c[1]), "+f"(c[2]), "+f"(c[3])
      : "r"(a[0]), "r"(a[1]), "r"(a[2]), "r"(a[3]), "r"(b[0]), "r"(b[1]));
}

// packed fp32x2 math
__device__ __forceinline__ unsigned long long pack2(float a) {
  unsigned long long r;
  asm("mov.b64 %0, {%1, %1};" : "=l"(r) : "r"(__float_as_uint(a)));
  return r;
}
__device__ __forceinline__ void fma2(unsigned long long& d,
                                     unsigned long long a, unsigned long long b) {
  asm("fma.rn.f32x2 %0, %1, %2, %0;" : "+l"(d) : "l"(a), "l"(b));
}
__device__ __forceinline__ float lo32(unsigned long long v) {
  return __uint_as_float((unsigned)v);
}
__device__ __forceinline__ float hi32(unsigned long long v) {
  return __uint_as_float((unsigned)(v >> 32));
}

__device__ __forceinline__ void split2(float a, float b, uint32_t& hi, uint32_t& lo) {
  __nv_bfloat16 ha = __float2bfloat16_rn(a);
  __nv_bfloat16 hb = __float2bfloat16_rn(b);
  float ra = a - __bfloat162float(ha);
  float rb = b - __bfloat162float(hb);
  __nv_bfloat162 th; th.x = ha; th.y = hb;
  __nv_bfloat162 tl; tl.x = __float2bfloat16_rn(ra); tl.y = __float2bfloat16_rn(rb);
  hi = *(uint32_t*)&th;
  lo = *(uint32_t*)&tl;
}

// ---------------------------------------------------------------------------
// Weight split kernel
// ---------------------------------------------------------------------------
__global__ __launch_bounds__(256) void split_kernel(
    const float* __restrict__ src, __nv_bfloat16* __restrict__ hi,
    __nv_bfloat16* __restrict__ lo, int n4) {
  int i = blockIdx.x * 256 + threadIdx.x;
  if (i >= n4) return;
  float4 v = ((const float4*)src)[i];
  uint32_t h0, l0, h1, l1;
  split2(v.x, v.y, h0, l0);
  split2(v.z, v.w, h1, l1);
  ((uint2*)hi)[i] = make_uint2(h0, h1);
  ((uint2*)lo)[i] = make_uint2(l0, l1);
}

// ---------------------------------------------------------------------------
// Kernel 1: channel LayerNorm + roll(-4,-4) + window partition -> bf16 hi/lo
// ---------------------------------------------------------------------------
__global__ __launch_bounds__(128) void ln_kernel(
    const float* __restrict__ x, const float* __restrict__ gamma,
    const float* __restrict__ beta) {
  __shared__ float gs[512], bs[512];
  for (int i = threadIdx.x; i < 512; i += 128) {
    gs[i] = gamma[i];
    bs[i] = beta[i];
  }
  __syncthreads();

  int b = blockIdx.x >> 7;
  int h = blockIdx.x & 127;
  int w = threadIdx.x;
  const float* p = x + (((size_t)b * 512) * 128 + h) * 128 + w;

  float s = 0.f, sq = 0.f;
#pragma unroll 8
  for (int d = 0; d < 512; d++) {
    float v = p[(size_t)d * 16384];
    s += v;
    sq = fmaf(v, v, sq);
  }
  float mean = s * (1.f / 512.f);
  float var = sq * (1.f / 512.f) - mean * mean;
  float rstd = rsqrtf(var + 1e-5f);

  int hp = (h + 124) & 127;
  int wp = (w + 124) & 127;
  int pix = ((((b << 4) + (hp >> 3)) << 4) + (wp >> 3)) * 64 + ((hp & 7) << 3) + (wp & 7);

  __nv_bfloat16* hrow = g_x_hi + (size_t)pix * 512;
  __nv_bfloat16* lrow = g_x_lo + (size_t)pix * 512;
#pragma unroll 2
  for (int d0 = 0; d0 < 512; d0 += 8) {
    uint32_t hw[4], lw[4];
#pragma unroll
    for (int j = 0; j < 4; j++) {
      int d = d0 + 2 * j;
      float v0 = (p[(size_t)d * 16384] - mean) * rstd * gs[d] + bs[d];
      float v1 = (p[(size_t)(d + 1) * 16384] - mean) * rstd * gs[d + 1] + bs[d + 1];
      split2(v0, v1, hw[j], lw[j]);
    }
    *(uint4*)(hrow + d0) = make_uint4(hw[0], hw[1], hw[2], hw[3]);
    *(uint4*)(lrow + d0) = make_uint4(lw[0], lw[1], lw[2], lw[3]);
  }
}

// ---------------------------------------------------------------------------
// mma.sync bf16 split-precision GEMM: CTA 128x128, 4 warps (2m x 2n),
// warp tile 64x64, BK=32, 2-stage cp.async (R6 rhythm), 128 threads.
// Stage: AH(10240) AL(10240) BH(10240) BL(10240) = 40960 B; 2 stages, row 80 B.
// Halves ldmatrix traffic per FLOP vs 64x32 warp tile while keeping 2 CTAs/SM.
// ---------------------------------------------------------------------------
#define STAGE_BYTES 40960
#define SMEM_BYTES (2 * STAGE_BYTES)

__device__ __forceinline__ void stage_load(
    const __nv_bfloat16* __restrict__ Ahi, const __nv_bfloat16* __restrict__ Alo,
    const __nv_bfloat16* __restrict__ Bhi, const __nv_bfloat16* __restrict__ Blo,
    int m0, int n0, int k0, uint32_t sstage, int tid) {
#pragma unroll
  for (int i = 0; i < 4; i++) {
    int g = i * 128 + tid;           // 0..511 (128 rows x 4 chunks)
    int row = g >> 2, c = g & 3;
    uint32_t off = (uint32_t)row * 80 + c * 16;
    size_t asrc = (size_t)(m0 + row) * 512 + k0 + c * 8;
    size_t bsrc = (size_t)(n0 + row) * 512 + k0 + c * 8;
    cpa16(sstage + off,         Ahi + asrc);
    cpa16(sstage + 10240 + off, Alo + asrc);
    cpa16(sstage + 20480 + off, Bhi + bsrc);
    cpa16(sstage + 30720 + off, Blo + bsrc);
  }
  asm volatile("cp.async.commit_group;");
}

template <bool FINAL>
__global__ __launch_bounds__(128, 2) void mma_gemm(
    const __nv_bfloat16* __restrict__ Ahi, const __nv_bfloat16* __restrict__ Alo,
    const __nv_bfloat16* __restrict__ Bhi, const __nv_bfloat16* __restrict__ Blo,
    const float* __restrict__ bias, float* __restrict__ outp) {
  extern __shared__ __align__(128) char smem[];
  const int tid = threadIdx.x;
  const int lane = tid & 31;
  const int warp = tid >> 5;
  const int wm = warp & 1;      // 0..1 (64 m each)
  const int wn = warp >> 1;     // 0..1 (64 n each)
  const int m0 = blockIdx.x << 7;  // m fastest -> weights stay L2-resident
  const int n0 = blockIdx.y << 7;
  const uint32_t sb = smem_u32(smem);

  const int arow = (lane & 7) + ((lane >> 3) & 1) * 8;
  const uint32_t aoff = (uint32_t)(wm * 64 + arow) * 80 + (lane >> 4) * 16;
  const int brow = (lane & 7) + (lane >> 4) * 8;
  const uint32_t bksel = ((lane >> 3) & 1) * 16;

  float acc[4][8][4];
#pragma unroll
  for (int mi = 0; mi < 4; mi++)
#pragma unroll
    for (int ni = 0; ni < 8; ni++)
#pragma unroll
      for (int r = 0; r < 4; r++) acc[mi][ni][r] = 0.f;

  stage_load(Ahi, Alo, Bhi, Blo, m0, n0, 0, sb, tid);

  for (int kc = 0; kc < 16; kc++) {
    const uint32_t cur = sb + (kc & 1) * STAGE_BYTES;
    if (kc < 15) {
      stage_load(Ahi, Alo, Bhi, Blo, m0, n0, (kc + 1) * 32,
                 sb + ((kc + 1) & 1) * STAGE_BYTES, tid);
      asm volatile("cp.async.wait_group 1;" ::: "memory");
    } else {
      asm volatile("cp.async.wait_group 0;" ::: "memory");
    }
    __syncthreads();

#pragma unroll
    for (int ks = 0; ks < 2; ks++) {
      uint32_t a_hi[4][4], a_lo[4][4];
#pragma unroll
      for (int mi = 0; mi < 4; mi++) {
        uint32_t ad = cur + aoff + (uint32_t)mi * (16 * 80) + ks * 32;
        ldsm4(a_hi[mi], ad);
        ldsm4(a_lo[mi], ad + 10240);
      }
      uint32_t b_hi[8][2], b_lo[8][2];
#pragma unroll
      for (int nj = 0; nj < 4; nj++) {
        uint32_t bd = cur + 20480 +
                      (uint32_t)(wn * 64 + nj * 16 + brow) * 80 + bksel + ks * 32;
        uint32_t t[4];
        ldsm4(t, bd);
        b_hi[2 * nj][0] = t[0]; b_hi[2 * nj][1] = t[1];
        b_hi[2 * nj + 1][0] = t[2]; b_hi[2 * nj + 1][1] = t[3];
        ldsm4(t, bd + 10240);
        b_lo[2 * nj][0] = t[0]; b_lo[2 * nj][1] = t[1];
        b_lo[2 * nj + 1][0] = t[2]; b_lo[2 * nj + 1][1] = t[3];
      }
#pragma unroll
      for (int mi = 0; mi < 4; mi++) {
#pragma unroll
        for (int ni = 0; ni < 8; ni++) {
          mma_bf16(acc[mi][ni], a_hi[mi], b_hi[ni]);
          mma_bf16(acc[mi][ni], a_hi[mi], b_lo[ni]);
          mma_bf16(acc[mi][ni], a_lo[mi], b_hi[ni]);
        }
      }
    }
    __syncthreads();
  }

  const int g = lane >> 2;
  const int t2 = (lane & 3) * 2;
  if (!FINAL) {
#pragma unroll
    for (int mi = 0; mi < 4; mi++) {
#pragma unroll
      for (int half = 0; half < 2; half++) {
        int e = m0 + wm * 64 + mi * 16 + g + half * 8;
        float* rowp = g_qkv + (size_t)e * NPIX;
#pragma unroll
        for (int ni = 0; ni < 8; ni++) {
          int pix = n0 + wn * 64 + ni * 8 + t2;
          float2 v;
          v.x = acc[mi][ni][2 * half + 0];
          v.y = acc[mi][ni][2 * half + 1];
          *(float2*)(rowp + pix) = v;
        }
      }
    }
  } else {
    size_t pbase[8];
#pragma unroll
    for (int ni = 0; ni < 8; ni++) {
      int pix = n0 + wn * 64 + ni * 8 + t2;
      int win = pix >> 6, l = pix & 63;
      int bb = win >> 8, wh = (win >> 4) & 15, ww = win & 15;
      int hh = ((wh << 3) + (l >> 3) + 4) & 127;
      int wcol = ((ww << 3) + (l & 7) + 4) & 127;
      pbase[ni] = (size_t)bb * 8388608 + (size_t)hh * 128 + wcol;
    }
#pragma unroll
    for (int mi = 0; mi < 4; mi++) {
#pragma unroll
      for (int half = 0; half < 2; half++) {
        int e = m0 + wm * 64 + mi * 16 + g + half * 8;
        float bv = __ldg(bias + e);
#pragma unroll
        for (int ni = 0; ni < 8; ni++) {
          float2 v;
          v.x = acc[mi][ni][2 * half + 0] + bv;
          v.y = acc[mi][ni][2 * half + 1] + bv;
          *(float2*)(outp + pbase[ni] + (size_t)e * 16384) = v;
        }
      }
    }
  }
}

// ---------------------------------------------------------------------------
// Kernel 3: per-(window, head) attention with RoPE, fp32 math via fma.rn.f32x2
// grid = 16384, block 256. thread = (i = tid&63 query row, g = tid>>6 quarter)
// ---------------------------------------------------------------------------
__global__ __launch_bounds__(256) void attn_kernel() {
  __shared__ float qs[64][36];
  __shared__ float ks[64][36];
  __shared__ float vs[64][32];
  __shared__ float lg[64][65];
  __shared__ float redm[64][4];
  __shared__ float reds[64][4];

  int tid = threadIdx.x;
  int win = blockIdx.x >> 4;
  int head = blockIdx.x & 15;
  const float* base = g_qkv + (size_t)(head * 32) * NPIX + (size_t)win * 64;

  {
    int dd = tid >> 3;
    int l0 = (tid & 7) << 3;
    const float* pq = base + (size_t)dd * NPIX + l0;
    const float* pk = pq + (size_t)512 * NPIX;
    const float* pv = pq + (size_t)1024 * NPIX;
    float4 u0 = *(const float4*)pq;
    float4 u1 = *(const float4*)(pq + 4);
    qs[l0 + 0][dd] = u0.x; qs[l0 + 1][dd] = u0.y;
    qs[l0 + 2][dd] = u0.z; qs[l0 + 3][dd] = u0.w;
    qs[l0 + 4][dd] = u1.x; qs[l0 + 5][dd] = u1.y;
    qs[l0 + 6][dd] = u1.z; qs[l0 + 7][dd] = u1.w;
    u0 = *(const float4*)pk;
    u1 = *(const float4*)(pk + 4);
    ks[l0 + 0][dd] = u0.x; ks[l0 + 1][dd] = u0.y;
    ks[l0 + 2][dd] = u0.z; ks[l0 + 3][dd] = u0.w;
    ks[l0 + 4][dd] = u1.x; ks[l0 + 5][dd] = u1.y;
    ks[l0 + 6][dd] = u1.z; ks[l0 + 7][dd] = u1.w;
    u0 = *(const float4*)pv;
    u1 = *(const float4*)(pv + 4);
    vs[l0 + 0][dd] = u0.x; vs[l0 + 1][dd] = u0.y;
    vs[l0 + 2][dd] = u0.z; vs[l0 + 3][dd] = u0.w;
    vs[l0 + 4][dd] = u1.x; vs[l0 + 5][dd] = u1.y;
    vs[l0 + 6][dd] = u1.z; vs[l0 + 7][dd] = u1.w;
  }
  __syncthreads();

#pragma unroll
  for (int it = 0; it < 4; it++) {
    int p = tid + it * 256;
    int l = p >> 4;
    int j = p & 15;
    int pos = (j < 8) ? (l >> 3) : (l & 7);
    int fj = j & 7;
    float freq = expf(-(float)fj * (9.210340371976184f / 8.0f));
    float th = (float)pos * freq;
    float c = cosf(th), s = sinf(th);
    float q0 = qs[l][j], q1 = qs[l][j + 16];
    qs[l][j] = q0 * c - q1 * s;
    qs[l][j + 16] = fmaf(q1, c, q0 * s);
    float k0 = ks[l][j], k1 = ks[l][j + 16];
    ks[l][j] = k0 * c - k1 * s;
    ks[l][j + 16] = fmaf(k1, c, k0 * s);
  }
  __syncthreads();

  int i = tid & 63;
  int g = tid >> 6;

  // q row cached as packed f32x2 (rows are 144 B => 8 B aligned)
  unsigned long long qp[16];
  {
    const unsigned long long* qrow = (const unsigned long long*)&qs[i][0];
#pragma unroll
    for (int d2 = 0; d2 < 16; d2++) qp[d2] = qrow[d2];
  }

  // logits for j in [g*16, g*16+16) with FFMA2
#pragma unroll
  for (int jj = 0; jj < 16; jj++) {
    int j = (g << 4) + jj;
    const unsigned long long* krow = (const unsigned long long*)&ks[j][0];
    unsigned long long acc2 = 0ull;
#pragma unroll
    for (int d2 = 0; d2 < 16; d2++) fma2(acc2, qp[d2], krow[d2]);
    lg[i][j] = (lo32(acc2) + hi32(acc2)) * 0.17677669529663687f;
  }
  __syncthreads();

  float mx = -1e30f;
#pragma unroll
  for (int jj = 0; jj < 16; jj++) mx = fmaxf(mx, lg[i][(g << 4) + jj]);
  redm[i][g] = mx;
  __syncthreads();
  mx = fmaxf(fmaxf(redm[i][0], redm[i][1]), fmaxf(redm[i][2], redm[i][3]));
  float sum = 0.f;
#pragma unroll
  for (int jj = 0; jj < 16; jj++) {
    int j = (g << 4) + jj;
    float e = __expf(lg[i][j] - mx);
    lg[i][j] = e;
    sum += e;
  }
  reds[i][g] = sum;
  __syncthreads();
  float inv = 1.0f / (reds[i][0] + reds[i][1] + reds[i][2] + reds[i][3]);

  // P @ V with FFMA2: thread covers dd in [g*8, g*8+8)
  unsigned long long o2[4] = {0ull, 0ull, 0ull, 0ull};
#pragma unroll 4
  for (int j = 0; j < 64; j++) {
    unsigned long long pv2 = pack2(lg[i][j] * inv);
    const unsigned long long* vp = (const unsigned long long*)&vs[j][g << 3];
    fma2(o2[0], pv2, vp[0]);
    fma2(o2[1], pv2, vp[1]);
    fma2(o2[2], pv2, vp[2]);
    fma2(o2[3], pv2, vp[3]);
  }

  size_t row = (size_t)win * 64 + i;
  int col = head * 32 + (g << 3);
  uint32_t hw[4], lw[4];
#pragma unroll
  for (int j = 0; j < 4; j++) split2(lo32(o2[j]), hi32(o2[j]), hw[j], lw[j]);
  *(uint4*)(g_ao_hi + row * 512 + col) = make_uint4(hw[0], hw[1], hw[2], hw[3]);
  *(uint4*)(g_ao_lo + row * 512 + col) = make_uint4(lw[0], lw[1], lw[2], lw[3]);
}

// ---------------------------------------------------------------------------
extern "C" void kernel_launch(void* const* d_in, const int* in_sizes, int n_in,
                              void* d_out, int out_size) {
  const float* x = (const float*)d_in[0];
  const float* ln_g = (const float*)d_in[1];
  const float* ln_b = (const float*)d_in[2];
  const float* w_qkv = (const float*)d_in[3];
  const float* w_out = (const float*)d_in[4];
  const float* b_out = (const float*)d_in[5];
  float* out = (float*)d_out;
  (void)in_sizes; (void)n_in; (void)out_size;

  cudaFuncSetAttribute(mma_gemm<false>, cudaFuncAttributeMaxDynamicSharedMemorySize, SMEM_BYTES);
  cudaFuncSetAttribute(mma_gemm<true>, cudaFuncAttributeMaxDynamicSharedMemorySize, SMEM_BYTES);

  __nv_bfloat16 *p_wq_hi, *p_wq_lo, *p_wo_hi, *p_wo_lo, *p_x_hi, *p_x_lo, *p_ao_hi, *p_ao_lo;
  cudaGetSymbolAddress((void**)&p_wq_hi, g_wq_hi);
  cudaGetSymbolAddress((void**)&p_wq_lo, g_wq_lo);
  cudaGetSymbolAddress((void**)&p_wo_hi, g_wo_hi);
  cudaGetSymbolAddress((void**)&p_wo_lo, g_wo_lo);
  cudaGetSymbolAddress((void**)&p_x_hi, g_x_hi);
  cudaGetSymbolAddress((void**)&p_x_lo, g_x_lo);
  cudaGetSymbolAddress((void**)&p_ao_hi, g_ao_hi);
  cudaGetSymbolAddress((void**)&p_ao_lo, g_ao_lo);

  split_kernel<<<(1536 * 512 / 4 + 255) / 256, 256>>>(w_qkv, p_wq_hi, p_wq_lo, 1536 * 512 / 4);
  split_kernel<<<(512 * 512 / 4 + 255) / 256, 256>>>(w_out, p_wo_hi, p_wo_lo, 512 * 512 / 4);
  ln_kernel<<<512, 128>>>(x, ln_g, ln_b);
  // A = weights (M rows), B = activations (N pix); m fastest keeps weights in L2
  mma_gemm<false><<<dim3(12, 512), 128, SMEM_BYTES>>>(p_wq_hi, p_wq_lo, p_x_hi, p_x_lo, nullptr, nullptr);
  attn_kernel<<<16384, 256>>>();
  mma_gemm<true><<<dim3(4, 512), 128, SMEM_BYTES>>>(p_wo_hi, p_wo_lo, p_ao_hi, p_ao_lo, b_out, out);
}

// round 16
// speedup vs baseline: 1.0021x; 1.0004x over previous
#include <cuda_runtime.h>
#include <cuda_bf16.h>
#include <cstdint>

#define NPIX 65536

// ---------------------------------------------------------------------------
// Device-global scratch (no runtime allocation allowed)
// ---------------------------------------------------------------------------
__device__ __nv_bfloat16 g_x_hi[512u * 65536u];   // [pix][512]
__device__ __nv_bfloat16 g_x_lo[512u * 65536u];
__device__ float         g_qkv[1536u * 65536u];   // [e][pix] fp32
__device__ __nv_bfloat16 g_ao_hi[512u * 65536u];  // [pix][512]
__device__ __nv_bfloat16 g_ao_lo[512u * 65536u];
__device__ __nv_bfloat16 g_wq_hi[1536u * 512u];   // [e][d]
__device__ __nv_bfloat16 g_wq_lo[1536u * 512u];
__device__ __nv_bfloat16 g_wo_hi[512u * 512u];
__device__ __nv_bfloat16 g_wo_lo[512u * 512u];

// ---------------------------------------------------------------------------
// PTX helpers
// ---------------------------------------------------------------------------
__device__ __forceinline__ uint32_t smem_u32(const void* p) {
  uint32_t a;
  asm("{ .reg .u64 t; cvta.to.shared.u64 t, %1; cvt.u32.u64 %0, t; }"
      : "=r"(a) : "l"(p));
  return a;
}
__device__ __forceinline__ void cpa16(uint32_t dst, const void* src) {
  asm volatile("cp.async.cg.shared.global [%0], [%1], 16;" :: "r"(dst), "l"(src));
}
__device__ __forceinline__ void ldsm4(uint32_t* r, uint32_t addr) {
  asm volatile("ldmatrix.sync.aligned.m8n8.x4.shared.b16 {%0,%1,%2,%3}, [%4];"
               : "=r"(r[0]), "=r"(r[1]), "=r"(r[2]), "=r"(r[3]) : "r"(addr));
}
__device__ __forceinline__ void mma_bf16(float* c, const uint32_t* a,
                                         const uint32_t* b) {
  asm volatile(
      "mma.sync.aligned.m16n8k16.row.col.f32.bf16.bf16.f32 "
      "{%0,%1,%2,%3}, {%4,%5,%6,%7}, {%8,%9}, {%0,%1,%2,%3};"
      : "+f"(c[0]), "+f"(c[1]), "+f"(c[2]), "+f"(c[3])
      : "r"(a[0]), "r"(a[1]), "r"(a[2]), "r"(a[3]), "r"(b[0]), "r"(b[1]));
}

// packed fp32x2 math
__device__ __forceinline__ unsigned long long pack2(float a) {
  unsigned long long r;
  asm("mov.b64 %0, {%1, %1};" : "=l"(r) : "r"(__float_as_uint(a)));
  return r;
}
__device__ __forceinline__ void fma2(unsigned long long& d,
                                     unsigned long long a, unsigned long long b) {
  asm("fma.rn.f32x2 %0, %1, %2, %0;" : "+l"(d) : "l"(a), "l"(b));
}
__device__ __forceinline__ float lo32(unsigned long long v) {
  return __uint_as_float((unsigned)v);
}
__device__ __forceinline__ float hi32(unsigned long long v) {
  return __uint_as_float((unsigned)(v >> 32));
}

__device__ __forceinline__ void split2(float a, float b, uint32_t& hi, uint32_t& lo) {
  __nv_bfloat16 ha = __float2bfloat16_rn(a);
  __nv_bfloat16 hb = __float2bfloat16_rn(b);
  float ra = a - __bfloat162float(ha);
  float rb = b - __bfloat162float(hb);
  __nv_bfloat162 th; th.x = ha; th.y = hb;
  __nv_bfloat162 tl; tl.x = __float2bfloat16_rn(ra); tl.y = __float2bfloat16_rn(rb);
  hi = *(uint32_t*)&th;
  lo = *(uint32_t*)&tl;
}

// ---------------------------------------------------------------------------
// Weight split kernel
// ---------------------------------------------------------------------------
__global__ __launch_bounds__(256) void split_kernel(
    const float* __restrict__ src, __nv_bfloat16* __restrict__ hi,
    __nv_bfloat16* __restrict__ lo, int n4) {
  int i = blockIdx.x * 256 + threadIdx.x;
  if (i >= n4) return;
  float4 v = ((const float4*)src)[i];
  uint32_t h0, l0, h1, l1;
  split2(v.x, v.y, h0, l0);
  split2(v.z, v.w, h1, l1);
  ((uint2*)hi)[i] = make_uint2(h0, h1);
  ((uint2*)lo)[i] = make_uint2(l0, l1);
}

// ---------------------------------------------------------------------------
// Kernel 1: channel LayerNorm + roll(-4,-4) + window partition -> bf16 hi/lo
// ---------------------------------------------------------------------------
__global__ __launch_bounds__(128) void ln_kernel(
    const float* __restrict__ x, const float* __restrict__ gamma,
    const float* __restrict__ beta) {
  __shared__ float gs[512], bs[512];
  for (int i = threadIdx.x; i < 512; i += 128) {
    gs[i] = gamma[i];
    bs[i] = beta[i];
  }
  __syncthreads();

  int b = blockIdx.x >> 7;
  int h = blockIdx.x & 127;
  int w = threadIdx.x;
  const float* p = x + (((size_t)b * 512) * 128 + h) * 128 + w;

  float s = 0.f, sq = 0.f;
#pragma unroll 8
  for (int d = 0; d < 512; d++) {
    float v = p[(size_t)d * 16384];
    s += v;
    sq = fmaf(v, v, sq);
  }
  float mean = s * (1.f / 512.f);
  float var = sq * (1.f / 512.f) - mean * mean;
  float rstd = rsqrtf(var + 1e-5f);

  int hp = (h + 124) & 127;
  int wp = (w + 124) & 127;
  int pix = ((((b << 4) + (hp >> 3)) << 4) + (wp >> 3)) * 64 + ((hp & 7) << 3) + (wp & 7);

  __nv_bfloat16* hrow = g_x_hi + (size_t)pix * 512;
  __nv_bfloat16* lrow = g_x_lo + (size_t)pix * 512;
#pragma unroll 2
  for (int d0 = 0; d0 < 512; d0 += 8) {
    uint32_t hw[4], lw[4];
#pragma unroll
    for (int j = 0; j < 4; j++) {
      int d = d0 + 2 * j;
      float v0 = (p[(size_t)d * 16384] - mean) * rstd * gs[d] + bs[d];
      float v1 = (p[(size_t)(d + 1) * 16384] - mean) * rstd * gs[d + 1] + bs[d + 1];
      split2(v0, v1, hw[j], lw[j]);
    }
    *(uint4*)(hrow + d0) = make_uint4(hw[0], hw[1], hw[2], hw[3]);
    *(uint4*)(lrow + d0) = make_uint4(lw[0], lw[1], lw[2], lw[3]);
  }
}

// ---------------------------------------------------------------------------
// mma.sync bf16 split-precision GEMM: CTA 128x128, 4 warps (2m x 2n),
// warp tile 64x64, BK=32, 2-stage cp.async (R6 rhythm), 128 threads.
// Stage: AH(10240) AL(10240) BH(10240) BL(10240) = 40960 B; 2 stages, row 80 B.
// Halves ldmatrix traffic per FLOP vs 64x32 warp tile while keeping 2 CTAs/SM.
// ---------------------------------------------------------------------------
#define STAGE_BYTES 40960
#define SMEM_BYTES (2 * STAGE_BYTES)

__device__ __forceinline__ void stage_load(
    const __nv_bfloat16* __restrict__ Ahi, const __nv_bfloat16* __restrict__ Alo,
    const __nv_bfloat16* __restrict__ Bhi, const __nv_bfloat16* __restrict__ Blo,
    int m0, int n0, int k0, uint32_t sstage, int tid) {
#pragma unroll
  for (int i = 0; i < 4; i++) {
    int g = i * 128 + tid;           // 0..511 (128 rows x 4 chunks)
    int row = g >> 2, c = g & 3;
    uint32_t off = (uint32_t)row * 80 + c * 16;
    size_t asrc = (size_t)(m0 + row) * 512 + k0 + c * 8;
    size_t bsrc = (size_t)(n0 + row) * 512 + k0 + c * 8;
    cpa16(sstage + off,         Ahi + asrc);
    cpa16(sstage + 10240 + off, Alo + asrc);
    cpa16(sstage + 20480 + off, Bhi + bsrc);
    cpa16(sstage + 30720 + off, Blo + bsrc);
  }
  asm volatile("cp.async.commit_group;");
}

template <bool FINAL>
__global__ __launch_bounds__(128, 2) void mma_gemm(
    const __nv_bfloat16* __restrict__ Ahi, const __nv_bfloat16* __restrict__ Alo,
    const __nv_bfloat16* __restrict__ Bhi, const __nv_bfloat16* __restrict__ Blo,
    const float* __restrict__ bias, float* __restrict__ outp) {
  extern __shared__ __align__(128) char smem[];
  const int tid = threadIdx.x;
  const int lane = tid & 31;
  const int warp = tid >> 5;
  const int wm = warp & 1;      // 0..1 (64 m each)
  const int wn = warp >> 1;     // 0..1 (64 n each)
  const int m0 = blockIdx.x << 7;  // m fastest -> weights stay L2-resident
  const int n0 = blockIdx.y << 7;
  const uint32_t sb = smem_u32(smem);

  const int arow = (lane & 7) + ((lane >> 3) & 1) * 8;
  const uint32_t aoff = (uint32_t)(wm * 64 + arow) * 80 + (lane >> 4) * 16;
  const int brow = (lane & 7) + (lane >> 4) * 8;
  const uint32_t bksel = ((lane >> 3) & 1) * 16;

  float acc[4][8][4];
#pragma unroll
  for (int mi = 0; mi < 4; mi++)
#pragma unroll
    for (int ni = 0; ni < 8; ni++)
#pragma unroll
      for (int r = 0; r < 4; r++) acc[mi][ni][r] = 0.f;

  stage_load(Ahi, Alo, Bhi, Blo, m0, n0, 0, sb, tid);

  for (int kc = 0; kc < 16; kc++) {
    const uint32_t cur = sb + (kc & 1) * STAGE_BYTES;
    if (kc < 15) {
      stage_load(Ahi, Alo, Bhi, Blo, m0, n0, (kc + 1) * 32,
                 sb + ((kc + 1) & 1) * STAGE_BYTES, tid);
      asm volatile("cp.async.wait_group 1;" ::: "memory");
    } else {
      asm volatile("cp.async.wait_group 0;" ::: "memory");
    }
    __syncthreads();

#pragma unroll
    for (int ks = 0; ks < 2; ks++) {
      uint32_t a_hi[4][4], a_lo[4][4];
#pragma unroll
      for (int mi = 0; mi < 4; mi++) {
        uint32_t ad = cur + aoff + (uint32_t)mi * (16 * 80) + ks * 32;
        ldsm4(a_hi[mi], ad);
        ldsm4(a_lo[mi], ad + 10240);
      }
      uint32_t b_hi[8][2], b_lo[8][2];
#pragma unroll
      for (int nj = 0; nj < 4; nj++) {
        uint32_t bd = cur + 20480 +
                      (uint32_t)(wn * 64 + nj * 16 + brow) * 80 + bksel + ks * 32;
        uint32_t t[4];
        ldsm4(t, bd);
        b_hi[2 * nj][0] = t[0]; b_hi[2 * nj][1] = t[1];
        b_hi[2 * nj + 1][0] = t[2]; b_hi[2 * nj + 1][1] = t[3];
        ldsm4(t, bd + 10240);
        b_lo[2 * nj][0] = t[0]; b_lo[2 * nj][1] = t[1];
        b_lo[2 * nj + 1][0] = t[2]; b_lo[2 * nj + 1][1] = t[3];
      }
#pragma unroll
      for (int mi = 0; mi < 4; mi++) {
#pragma unroll
        for (int ni = 0; ni < 8; ni++) {
          mma_bf16(acc[mi][ni], a_hi[mi], b_hi[ni]);
          mma_bf16(acc[mi][ni], a_hi[mi], b_lo[ni]);
          mma_bf16(acc[mi][ni], a_lo[mi], b_hi[ni]);
        }
      }
    }
    __syncthreads();
  }

  const int g = lane >> 2;
  const int t2 = (lane & 3) * 2;
  if (!FINAL) {
#pragma unroll
    for (int mi = 0; mi < 4; mi++) {
#pragma unroll
      for (int half = 0; half < 2; half++) {
        int e = m0 + wm * 64 + mi * 16 + g + half * 8;
        float* rowp = g_qkv + (size_t)e * NPIX;
#pragma unroll
        for (int ni = 0; ni < 8; ni++) {
          int pix = n0 + wn * 64 + ni * 8 + t2;
          float2 v;
          v.x = acc[mi][ni][2 * half + 0];
          v.y = acc[mi][ni][2 * half + 1];
          *(float2*)(rowp + pix) = v;
        }
      }
    }
  } else {
    size_t pbase[8];
#pragma unroll
    for (int ni = 0; ni < 8; ni++) {
      int pix = n0 + wn * 64 + ni * 8 + t2;
      int win = pix >> 6, l = pix & 63;
      int bb = win >> 8, wh = (win >> 4) & 15, ww = win & 15;
      int hh = ((wh << 3) + (l >> 3) + 4) & 127;
      int wcol = ((ww << 3) + (l & 7) + 4) & 127;
      pbase[ni] = (size_t)bb * 8388608 + (size_t)hh * 128 + wcol;
    }
#pragma unroll
    for (int mi = 0; mi < 4; mi++) {
#pragma unroll
      for (int half = 0; half < 2; half++) {
        int e = m0 + wm * 64 + mi * 16 + g + half * 8;
        float bv = __ldg(bias + e);
#pragma unroll
        for (int ni = 0; ni < 8; ni++) {
          float2 v;
          v.x = acc[mi][ni][2 * half + 0] + bv;
          v.y = acc[mi][ni][2 * half + 1] + bv;
          *(float2*)(outp + pbase[ni] + (size_t)e * 16384) = v;
        }
      }
    }
  }
}

// ---------------------------------------------------------------------------
// Kernel 3: per-(window, head) attention with RoPE, fp32 math via fma.rn.f32x2
// grid = 16384, block 256. thread = (i = tid&63 query row, g = tid>>6 quarter)
// ---------------------------------------------------------------------------
__global__ __launch_bounds__(256) void attn_kernel() {
  __shared__ float qs[64][36];
  __shared__ float ks[64][36];
  __shared__ float vs[64][32];
  __shared__ float lg[64][65];
  __shared__ float redm[64][4];
  __shared__ float reds[64][4];

  int tid = threadIdx.x;
  int win = blockIdx.x >> 4;
  int head = blockIdx.x & 15;
  const float* base = g_qkv + (size_t)(head * 32) * NPIX + (size_t)win * 64;

  {
    int dd = tid >> 3;
    int l0 = (tid & 7) << 3;
    const float* pq = base + (size_t)dd * NPIX + l0;
    const float* pk = pq + (size_t)512 * NPIX;
    const float* pv = pq + (size_t)1024 * NPIX;
    float4 u0 = *(const float4*)pq;
    float4 u1 = *(const float4*)(pq + 4);
    qs[l0 + 0][dd] = u0.x; qs[l0 + 1][dd] = u0.y;
    qs[l0 + 2][dd] = u0.z; qs[l0 + 3][dd] = u0.w;
    qs[l0 + 4][dd] = u1.x; qs[l0 + 5][dd] = u1.y;
    qs[l0 + 6][dd] = u1.z; qs[l0 + 7][dd] = u1.w;
    u0 = *(const float4*)pk;
    u1 = *(const float4*)(pk + 4);
    ks[l0 + 0][dd] = u0.x; ks[l0 + 1][dd] = u0.y;
    ks[l0 + 2][dd] = u0.z; ks[l0 + 3][dd] = u0.w;
    ks[l0 + 4][dd] = u1.x; ks[l0 + 5][dd] = u1.y;
    ks[l0 + 6][dd] = u1.z; ks[l0 + 7][dd] = u1.w;
    u0 = *(const float4*)pv;
    u1 = *(const float4*)(pv + 4);
    vs[l0 + 0][dd] = u0.x; vs[l0 + 1][dd] = u0.y;
    vs[l0 + 2][dd] = u0.z; vs[l0 + 3][dd] = u0.w;
    vs[l0 + 4][dd] = u1.x; vs[l0 + 5][dd] = u1.y;
    vs[l0 + 6][dd] = u1.z; vs[l0 + 7][dd] = u1.w;
  }
  __syncthreads();

#pragma unroll
  for (int it = 0; it < 4; it++) {
    int p = tid + it * 256;
    int l = p >> 4;
    int j = p & 15;
    int pos = (j < 8) ? (l >> 3) : (l & 7);
    int fj = j & 7;
    float freq = expf(-(float)fj * (9.210340371976184f / 8.0f));
    float th = (float)pos * freq;
    float c = cosf(th), s = sinf(th);
    float q0 = qs[l][j], q1 = qs[l][j + 16];
    qs[l][j] = q0 * c - q1 * s;
    qs[l][j + 16] = fmaf(q1, c, q0 * s);
    float k0 = ks[l][j], k1 = ks[l][j + 16];
    ks[l][j] = k0 * c - k1 * s;
    ks[l][j + 16] = fmaf(k1, c, k0 * s);
  }
  __syncthreads();

  int i = tid & 63;
  int g = tid >> 6;

  // q row cached as packed f32x2 (rows are 144 B => 8 B aligned)
  unsigned long long qp[16];
  {
    const unsigned long long* qrow = (const unsigned long long*)&qs[i][0];
#pragma unroll
    for (int d2 = 0; d2 < 16; d2++) qp[d2] = qrow[d2];
  }

  // logits for j in [g*16, g*16+16) with FFMA2
#pragma unroll
  for (int jj = 0; jj < 16; jj++) {
    int j = (g << 4) + jj;
    const unsigned long long* krow = (const unsigned long long*)&ks[j][0];
    unsigned long long acc2 = 0ull;
#pragma unroll
    for (int d2 = 0; d2 < 16; d2++) fma2(acc2, qp[d2], krow[d2]);
    lg[i][j] = (lo32(acc2) + hi32(acc2)) * 0.17677669529663687f;
  }
  __syncthreads();

  float mx = -1e30f;
#pragma unroll
  for (int jj = 0; jj < 16; jj++) mx = fmaxf(mx, lg[i][(g << 4) + jj]);
  redm[i][g] = mx;
  __syncthreads();
  mx = fmaxf(fmaxf(redm[i][0], redm[i][1]), fmaxf(redm[i][2], redm[i][3]));
  float sum = 0.f;
#pragma unroll
  for (int jj = 0; jj < 16; jj++) {
    int j = (g << 4) + jj;
    float e = __expf(lg[i][j] - mx);
    lg[i][j] = e;
    sum += e;
  }
  reds[i][g] = sum;
  __syncthreads();
  float inv = 1.0f / (reds[i][0] + reds[i][1] + reds[i][2] + reds[i][3]);

  // P @ V with FFMA2: thread covers dd in [g*8, g*8+8)
  unsigned long long o2[4] = {0ull, 0ull, 0ull, 0ull};
#pragma unroll 4
  for (int j = 0; j < 64; j++) {
    unsigned long long pv2 = pack2(lg[i][j] * inv);
    const unsigned long long* vp = (const unsigned long long*)&vs[j][g << 3];
    fma2(o2[0], pv2, vp[0]);
    fma2(o2[1], pv2, vp[1]);
    fma2(o2[2], pv2, vp[2]);
    fma2(o2[3], pv2, vp[3]);
  }

  size_t row = (size_t)win * 64 + i;
  int col = head * 32 + (g << 3);
  uint32_t hw[4], lw[4];
#pragma unroll
  for (int j = 0; j < 4; j++) split2(lo32(o2[j]), hi32(o2[j]), hw[j], lw[j]);
  *(uint4*)(g_ao_hi + row * 512 + col) = make_uint4(hw[0], hw[1], hw[2], hw[3]);
  *(uint4*)(g_ao_lo + row * 512 + col) = make_uint4(lw[0], lw[1], lw[2], lw[3]);
}

// ---------------------------------------------------------------------------
extern "C" void kernel_launch(void* const* d_in, const int* in_sizes, int n_in,
                              void* d_out, int out_size) {
  const float* x = (const float*)d_in[0];
  const float* ln_g = (const float*)d_in[1];
  const float* ln_b = (const float*)d_in[2];
  const float* w_qkv = (const float*)d_in[3];
  const float* w_out = (const float*)d_in[4];
  const float* b_out = (const float*)d_in[5];
  float* out = (float*)d_out;
  (void)in_sizes; (void)n_in; (void)out_size;

  cudaFuncSetAttribute(mma_gemm<false>, cudaFuncAttributeMaxDynamicSharedMemorySize, SMEM_BYTES);
  cudaFuncSetAttribute(mma_gemm<true>, cudaFuncAttributeMaxDynamicSharedMemorySize, SMEM_BYTES);

  __nv_bfloat16 *p_wq_hi, *p_wq_lo, *p_wo_hi, *p_wo_lo, *p_x_hi, *p_x_lo, *p_ao_hi, *p_ao_lo;
  cudaGetSymbolAddress((void**)&p_wq_hi, g_wq_hi);
  cudaGetSymbolAddress((void**)&p_wq_lo, g_wq_lo);
  cudaGetSymbolAddress((void**)&p_wo_hi, g_wo_hi);
  cudaGetSymbolAddress((void**)&p_wo_lo, g_wo_lo);
  cudaGetSymbolAddress((void**)&p_x_hi, g_x_hi);
  cudaGetSymbolAddress((void**)&p_x_lo, g_x_lo);
  cudaGetSymbolAddress((void**)&p_ao_hi, g_ao_hi);
  cudaGetSymbolAddress((void**)&p_ao_lo, g_ao_lo);

  split_kernel<<<(1536 * 512 / 4 + 255) / 256, 256>>>(w_qkv, p_wq_hi, p_wq_lo, 1536 * 512 / 4);
  split_kernel<<<(512 * 512 / 4 + 255) / 256, 256>>>(w_out, p_wo_hi, p_wo_lo, 512 * 512 / 4);
  ln_kernel<<<512, 128>>>(x, ln_g, ln_b);
  // A = weights (M rows), B = activations (N pix); m fastest keeps weights in L2
  mma_gemm<false><<<dim3(12, 512), 128, SMEM_BYTES>>>(p_wq_hi, p_wq_lo, p_x_hi, p_x_lo, nullptr, nullptr);
  attn_kernel<<<16384, 256>>>();
  mma_gemm<true><<<dim3(4, 512), 128, SMEM_BYTES>>>(p_wo_hi, p_wo_lo, p_ao_hi, p_ao_lo, b_out, out);
}

// round 17
// speedup vs baseline: 1.0035x; 1.0014x over previous
#include <cuda_runtime.h>
#include <cuda_bf16.h>
#include <cstdint>

#define NPIX 65536

// ---------------------------------------------------------------------------
// Device-global scratch (no runtime allocation allowed)
// ---------------------------------------------------------------------------
__device__ __nv_bfloat16 g_x_hi[512u * 65536u];   // [pix][512]
__device__ __nv_bfloat16 g_x_lo[512u * 65536u];
__device__ float         g_qkv[1536u * 65536u];   // [e][pix] fp32
__device__ __nv_bfloat16 g_ao_hi[512u * 65536u];  // [pix][512]
__device__ __nv_bfloat16 g_ao_lo[512u * 65536u];
__device__ __nv_bfloat16 g_wq_hi[1536u * 512u];   // [e][d]
__device__ __nv_bfloat16 g_wq_lo[1536u * 512u];
__device__ __nv_bfloat16 g_wo_hi[512u * 512u];
__device__ __nv_bfloat16 g_wo_lo[512u * 512u];

// ---------------------------------------------------------------------------
// PTX helpers
// ---------------------------------------------------------------------------
__device__ __forceinline__ uint32_t smem_u32(const void* p) {
  uint32_t a;
  asm("{ .reg .u64 t; cvta.to.shared.u64 t, %1; cvt.u32.u64 %0, t; }"
      : "=r"(a) : "l"(p));
  return a;
}
__device__ __forceinline__ void cpa16(uint32_t dst, const void* src) {
  asm volatile("cp.async.cg.shared.global [%0], [%1], 16;" :: "r"(dst), "l"(src));
}
__device__ __forceinline__ void ldsm4(uint32_t* r, uint32_t addr) {
  asm volatile("ldmatrix.sync.aligned.m8n8.x4.shared.b16 {%0,%1,%2,%3}, [%4];"
               : "=r"(r[0]), "=r"(r[1]), "=r"(r[2]), "=r"(r[3]) : "r"(addr));
}
__device__ __forceinline__ void mma_bf16(float* c, const uint32_t* a,
                                         const uint32_t* b) {
  asm volatile(
      "mma.sync.aligned.m16n8k16.row.col.f32.bf16.bf16.f32 "
      "{%0,%1,%2,%3}, {%4,%5,%6,%7}, {%8,%9}, {%0,%1,%2,%3};"
      : "+f"(c[0]), "+f"(c[1]), "+f"(c[2]), "+f"(c[3])
      : "r"(a[0]), "r"(a[1]), "r"(a[2]), "r"(a[3]), "r"(b[0]), "r"(b[1]));
}

// packed fp32x2 math
__device__ __forceinline__ unsigned long long pack2(float a) {
  unsigned long long r;
  asm("mov.b64 %0, {%1, %1};" : "=l"(r) : "r"(__float_as_uint(a)));
  return r;
}
__device__ __forceinline__ void fma2(unsigned long long& d,
                                     unsigned long long a, unsigned long long b) {
  asm("fma.rn.f32x2 %0, %1, %2, %0;" : "+l"(d) : "l"(a), "l"(b));
}
__device__ __forceinline__ float lo32(unsigned long long v) {
  return __uint_as_float((unsigned)v);
}
__device__ __forceinline__ float hi32(unsigned long long v) {
  return __uint_as_float((unsigned)(v >> 32));
}

__device__ __forceinline__ void split2(float a, float b, uint32_t& hi, uint32_t& lo) {
  __nv_bfloat16 ha = __float2bfloat16_rn(a);
  __nv_bfloat16 hb = __float2bfloat16_rn(b);
  float ra = a - __bfloat162float(ha);
  float rb = b - __bfloat162float(hb);
  __nv_bfloat162 th; th.x = ha; th.y = hb;
  __nv_bfloat162 tl; tl.x = __float2bfloat16_rn(ra); tl.y = __float2bfloat16_rn(rb);
  hi = *(uint32_t*)&th;
  lo = *(uint32_t*)&tl;
}

// ---------------------------------------------------------------------------
// Weight split kernel
// ---------------------------------------------------------------------------
__global__ __launch_bounds__(256) void split_kernel(
    const float* __restrict__ src, __nv_bfloat16* __restrict__ hi,
    __nv_bfloat16* __restrict__ lo, int n4) {
  int i = blockIdx.x * 256 + threadIdx.x;
  if (i >= n4) return;
  float4 v = ((const float4*)src)[i];
  uint32_t h0, l0, h1, l1;
  split2(v.x, v.y, h0, l0);
  split2(v.z, v.w, h1, l1);
  ((uint2*)hi)[i] = make_uint2(h0, h1);
  ((uint2*)lo)[i] = make_uint2(l0, l1);
}

// ---------------------------------------------------------------------------
// Kernel 1: channel LayerNorm + roll(-4,-4) + window partition -> bf16 hi/lo
// ---------------------------------------------------------------------------
__global__ __launch_bounds__(128) void ln_kernel(
    const float* __restrict__ x, const float* __restrict__ gamma,
    const float* __restrict__ beta) {
  __shared__ float gs[512], bs[512];
  for (int i = threadIdx.x; i < 512; i += 128) {
    gs[i] = gamma[i];
    bs[i] = beta[i];
  }
  __syncthreads();

  int b = blockIdx.x >> 7;
  int h = blockIdx.x & 127;
  int w = threadIdx.x;
  const float* p = x + (((size_t)b * 512) * 128 + h) * 128 + w;

  float s = 0.f, sq = 0.f;
#pragma unroll 8
  for (int d = 0; d < 512; d++) {
    float v = p[(size_t)d * 16384];
    s += v;
    sq = fmaf(v, v, sq);
  }
  float mean = s * (1.f / 512.f);
  float var = sq * (1.f / 512.f) - mean * mean;
  float rstd = rsqrtf(var + 1e-5f);

  int hp = (h + 124) & 127;
  int wp = (w + 124) & 127;
  int pix = ((((b << 4) + (hp >> 3)) << 4) + (wp >> 3)) * 64 + ((hp & 7) << 3) + (wp & 7);

  __nv_bfloat16* hrow = g_x_hi + (size_t)pix * 512;
  __nv_bfloat16* lrow = g_x_lo + (size_t)pix * 512;
#pragma unroll 2
  for (int d0 = 0; d0 < 512; d0 += 8) {
    uint32_t hw[4], lw[4];
#pragma unroll
    for (int j = 0; j < 4; j++) {
      int d = d0 + 2 * j;
      float v0 = (p[(size_t)d * 16384] - mean) * rstd * gs[d] + bs[d];
      float v1 = (p[(size_t)(d + 1) * 16384] - mean) * rstd * gs[d + 1] + bs[d + 1];
      split2(v0, v1, hw[j], lw[j]);
    }
    *(uint4*)(hrow + d0) = make_uint4(hw[0], hw[1], hw[2], hw[3]);
    *(uint4*)(lrow + d0) = make_uint4(lw[0], lw[1], lw[2], lw[3]);
  }
}

// ---------------------------------------------------------------------------
// mma.sync bf16 split-precision GEMM: CTA 128x128, 4 warps (2m x 2n),
// warp tile 64x64, BK=32, 2-stage cp.async (R6 rhythm), 128 threads.
// Stage: AH(10240) AL(10240) BH(10240) BL(10240) = 40960 B; 2 stages, row 80 B.
// Halves ldmatrix traffic per FLOP vs 64x32 warp tile while keeping 2 CTAs/SM.
// ---------------------------------------------------------------------------
#define STAGE_BYTES 40960
#define SMEM_BYTES (2 * STAGE_BYTES)

__device__ __forceinline__ void stage_load(
    const __nv_bfloat16* __restrict__ Ahi, const __nv_bfloat16* __restrict__ Alo,
    const __nv_bfloat16* __restrict__ Bhi, const __nv_bfloat16* __restrict__ Blo,
    int m0, int n0, int k0, uint32_t sstage, int tid) {
#pragma unroll
  for (int i = 0; i < 4; i++) {
    int g = i * 128 + tid;           // 0..511 (128 rows x 4 chunks)
    int row = g >> 2, c = g & 3;
    uint32_t off = (uint32_t)row * 80 + c * 16;
    size_t asrc = (size_t)(m0 + row) * 512 + k0 + c * 8;
    size_t bsrc = (size_t)(n0 + row) * 512 + k0 + c * 8;
    cpa16(sstage + off,         Ahi + asrc);
    cpa16(sstage + 10240 + off, Alo + asrc);
    cpa16(sstage + 20480 + off, Bhi + bsrc);
    cpa16(sstage + 30720 + off, Blo + bsrc);
  }
  asm volatile("cp.async.commit_group;");
}

template <bool FINAL>
__global__ __launch_bounds__(128, 2) void mma_gemm(
    const __nv_bfloat16* __restrict__ Ahi, const __nv_bfloat16* __restrict__ Alo,
    const __nv_bfloat16* __restrict__ Bhi, const __nv_bfloat16* __restrict__ Blo,
    const float* __restrict__ bias, float* __restrict__ outp) {
  extern __shared__ __align__(128) char smem[];
  const int tid = threadIdx.x;
  const int lane = tid & 31;
  const int warp = tid >> 5;
  const int wm = warp & 1;      // 0..1 (64 m each)
  const int wn = warp >> 1;     // 0..1 (64 n each)
  const int m0 = blockIdx.x << 7;  // m fastest -> weights stay L2-resident
  const int n0 = blockIdx.y << 7;
  const uint32_t sb = smem_u32(smem);

  const int arow = (lane & 7) + ((lane >> 3) & 1) * 8;
  const uint32_t aoff = (uint32_t)(wm * 64 + arow) * 80 + (lane >> 4) * 16;
  const int brow = (lane & 7) + (lane >> 4) * 8;
  const uint32_t bksel = ((lane >> 3) & 1) * 16;

  float acc[4][8][4];
#pragma unroll
  for (int mi = 0; mi < 4; mi++)
#pragma unroll
    for (int ni = 0; ni < 8; ni++)
#pragma unroll
      for (int r = 0; r < 4; r++) acc[mi][ni][r] = 0.f;

  stage_load(Ahi, Alo, Bhi, Blo, m0, n0, 0, sb, tid);

  for (int kc = 0; kc < 16; kc++) {
    const uint32_t cur = sb + (kc & 1) * STAGE_BYTES;
    if (kc < 15) {
      stage_load(Ahi, Alo, Bhi, Blo, m0, n0, (kc + 1) * 32,
                 sb + ((kc + 1) & 1) * STAGE_BYTES, tid);
      asm volatile("cp.async.wait_group 1;" ::: "memory");
    } else {
      asm volatile("cp.async.wait_group 0;" ::: "memory");
    }
    __syncthreads();

#pragma unroll
    for (int ks = 0; ks < 2; ks++) {
      uint32_t a_hi[4][4], a_lo[4][4];
#pragma unroll
      for (int mi = 0; mi < 4; mi++) {
        uint32_t ad = cur + aoff + (uint32_t)mi * (16 * 80) + ks * 32;
        ldsm4(a_hi[mi], ad);
        ldsm4(a_lo[mi], ad + 10240);
      }
      uint32_t b_hi[8][2], b_lo[8][2];
#pragma unroll
      for (int nj = 0; nj < 4; nj++) {
        uint32_t bd = cur + 20480 +
                      (uint32_t)(wn * 64 + nj * 16 + brow) * 80 + bksel + ks * 32;
        uint32_t t[4];
        ldsm4(t, bd);
        b_hi[2 * nj][0] = t[0]; b_hi[2 * nj][1] = t[1];
        b_hi[2 * nj + 1][0] = t[2]; b_hi[2 * nj + 1][1] = t[3];
        ldsm4(t, bd + 10240);
        b_lo[2 * nj][0] = t[0]; b_lo[2 * nj][1] = t[1];
        b_lo[2 * nj + 1][0] = t[2]; b_lo[2 * nj + 1][1] = t[3];
      }
#pragma unroll
      for (int mi = 0; mi < 4; mi++) {
#pragma unroll
        for (int ni = 0; ni < 8; ni++) {
          mma_bf16(acc[mi][ni], a_hi[mi], b_hi[ni]);
          mma_bf16(acc[mi][ni], a_hi[mi], b_lo[ni]);
          mma_bf16(acc[mi][ni], a_lo[mi], b_hi[ni]);
        }
      }
    }
    __syncthreads();
  }

  const int g = lane >> 2;
  const int t2 = (lane & 3) * 2;
  if (!FINAL) {
#pragma unroll
    for (int mi = 0; mi < 4; mi++) {
#pragma unroll
      for (int half = 0; half < 2; half++) {
        int e = m0 + wm * 64 + mi * 16 + g + half * 8;
        float* rowp = g_qkv + (size_t)e * NPIX;
#pragma unroll
        for (int ni = 0; ni < 8; ni++) {
          int pix = n0 + wn * 64 + ni * 8 + t2;
          float2 v;
          v.x = acc[mi][ni][2 * half + 0];
          v.y = acc[mi][ni][2 * half + 1];
          *(float2*)(rowp + pix) = v;
        }
      }
    }
  } else {
    size_t pbase[8];
#pragma unroll
    for (int ni = 0; ni < 8; ni++) {
      int pix = n0 + wn * 64 + ni * 8 + t2;
      int win = pix >> 6, l = pix & 63;
      int bb = win >> 8, wh = (win >> 4) & 15, ww = win & 15;
      int hh = ((wh << 3) + (l >> 3) + 4) & 127;
      int wcol = ((ww << 3) + (l & 7) + 4) & 127;
      pbase[ni] = (size_t)bb * 8388608 + (size_t)hh * 128 + wcol;
    }
#pragma unroll
    for (int mi = 0; mi < 4; mi++) {
#pragma unroll
      for (int half = 0; half < 2; half++) {
        int e = m0 + wm * 64 + mi * 16 + g + half * 8;
        float bv = __ldg(bias + e);
#pragma unroll
        for (int ni = 0; ni < 8; ni++) {
          float2 v;
          v.x = acc[mi][ni][2 * half + 0] + bv;
          v.y = acc[mi][ni][2 * half + 1] + bv;
          *(float2*)(outp + pbase[ni] + (size_t)e * 16384) = v;
        }
      }
    }
  }
}

// ---------------------------------------------------------------------------
// Kernel 3: per-(window, head) attention with RoPE, fp32 math via fma.rn.f32x2
// grid = 16384, block 256. thread = (i = tid&63 query row, g = tid>>6 quarter)
// ---------------------------------------------------------------------------
__global__ __launch_bounds__(256) void attn_kernel() {
  __shared__ float qs[64][36];
  __shared__ float ks[64][36];
  __shared__ float vs[64][32];
  __shared__ float lg[64][65];
  __shared__ float redm[64][4];
  __shared__ float reds[64][4];

  int tid = threadIdx.x;
  int win = blockIdx.x >> 4;
  int head = blockIdx.x & 15;
  const float* base = g_qkv + (size_t)(head * 32) * NPIX + (size_t)win * 64;

  {
    int dd = tid >> 3;
    int l0 = (tid & 7) << 3;
    const float* pq = base + (size_t)dd * NPIX + l0;
    const float* pk = pq + (size_t)512 * NPIX;
    const float* pv = pq + (size_t)1024 * NPIX;
    float4 u0 = *(const float4*)pq;
    float4 u1 = *(const float4*)(pq + 4);
    qs[l0 + 0][dd] = u0.x; qs[l0 + 1][dd] = u0.y;
    qs[l0 + 2][dd] = u0.z; qs[l0 + 3][dd] = u0.w;
    qs[l0 + 4][dd] = u1.x; qs[l0 + 5][dd] = u1.y;
    qs[l0 + 6][dd] = u1.z; qs[l0 + 7][dd] = u1.w;
    u0 = *(const float4*)pk;
    u1 = *(const float4*)(pk + 4);
    ks[l0 + 0][dd] = u0.x; ks[l0 + 1][dd] = u0.y;
    ks[l0 + 2][dd] = u0.z; ks[l0 + 3][dd] = u0.w;
    ks[l0 + 4][dd] = u1.x; ks[l0 + 5][dd] = u1.y;
    ks[l0 + 6][dd] = u1.z; ks[l0 + 7][dd] = u1.w;
    u0 = *(const float4*)pv;
    u1 = *(const float4*)(pv + 4);
    vs[l0 + 0][dd] = u0.x; vs[l0 + 1][dd] = u0.y;
    vs[l0 + 2][dd] = u0.z; vs[l0 + 3][dd] = u0.w;
    vs[l0 + 4][dd] = u1.x; vs[l0 + 5][dd] = u1.y;
    vs[l0 + 6][dd] = u1.z; vs[l0 + 7][dd] = u1.w;
  }
  __syncthreads();

#pragma unroll
  for (int it = 0; it < 4; it++) {
    int p = tid + it * 256;
    int l = p >> 4;
    int j = p & 15;
    int pos = (j < 8) ? (l >> 3) : (l & 7);
    int fj = j & 7;
    float freq = expf(-(float)fj * (9.210340371976184f / 8.0f));
    float th = (float)pos * freq;
    float c = cosf(th), s = sinf(th);
    float q0 = qs[l][j], q1 = qs[l][j + 16];
    qs[l][j] = q0 * c - q1 * s;
    qs[l][j + 16] = fmaf(q1, c, q0 * s);
    float k0 = ks[l][j], k1 = ks[l][j + 16];
    ks[l][j] = k0 * c - k1 * s;
    ks[l][j + 16] = fmaf(k1, c, k0 * s);
  }
  __syncthreads();

  int i = tid & 63;
  int g = tid >> 6;

  // q row cached as packed f32x2 (rows are 144 B => 8 B aligned)
  unsigned long long qp[16];
  {
    const unsigned long long* qrow = (const unsigned long long*)&qs[i][0];
#pragma unroll
    for (int d2 = 0; d2 < 16; d2++) qp[d2] = qrow[d2];
  }

  // logits for j in [g*16, g*16+16) with FFMA2
#pragma unroll
  for (int jj = 0; jj < 16; jj++) {
    int j = (g << 4) + jj;
    const unsigned long long* krow = (const unsigned long long*)&ks[j][0];
    unsigned long long acc2 = 0ull;
#pragma unroll
    for (int d2 = 0; d2 < 16; d2++) fma2(acc2, qp[d2], krow[d2]);
    lg[i][j] = (lo32(acc2) + hi32(acc2)) * 0.17677669529663687f;
  }
  __syncthreads();

  float mx = -1e30f;
#pragma unroll
  for (int jj = 0; jj < 16; jj++) mx = fmaxf(mx, lg[i][(g << 4) + jj]);
  redm[i][g] = mx;
  __syncthreads();
  mx = fmaxf(fmaxf(redm[i][0], redm[i][1]), fmaxf(redm[i][2], redm[i][3]));
  float sum = 0.f;
#pragma unroll
  for (int jj = 0; jj < 16; jj++) {
    int j = (g << 4) + jj;
    float e = __expf(lg[i][j] - mx);
    lg[i][j] = e;
    sum += e;
  }
  reds[i][g] = sum;
  __syncthreads();
  float inv = 1.0f / (reds[i][0] + reds[i][1] + reds[i][2] + reds[i][3]);

  // P @ V with FFMA2: thread covers dd in [g*8, g*8+8)
  unsigned long long o2[4] = {0ull, 0ull, 0ull, 0ull};
#pragma unroll 4
  for (int j = 0; j < 64; j++) {
    unsigned long long pv2 = pack2(lg[i][j] * inv);
    const unsigned long long* vp = (const unsigned long long*)&vs[j][g << 3];
    fma2(o2[0], pv2, vp[0]);
    fma2(o2[1], pv2, vp[1]);
    fma2(o2[2], pv2, vp[2]);
    fma2(o2[3], pv2, vp[3]);
  }

  size_t row = (size_t)win * 64 + i;
  int col = head * 32 + (g << 3);
  uint32_t hw[4], lw[4];
#pragma unroll
  for (int j = 0; j < 4; j++) split2(lo32(o2[j]), hi32(o2[j]), hw[j], lw[j]);
  *(uint4*)(g_ao_hi + row * 512 + col) = make_uint4(hw[0], hw[1], hw[2], hw[3]);
  *(uint4*)(g_ao_lo + row * 512 + col) = make_uint4(lw[0], lw[1], lw[2], lw[3]);
}

// ---------------------------------------------------------------------------
extern "C" void kernel_launch(void* const* d_in, const int* in_sizes, int n_in,
                              void* d_out, int out_size) {
  const float* x = (const float*)d_in[0];
  const float* ln_g = (const float*)d_in[1];
  const float* ln_b = (const float*)d_in[2];
  const float* w_qkv = (const float*)d_in[3];
  const float* w_out = (const float*)d_in[4];
  const float* b_out = (const float*)d_in[5];
  float* out = (float*)d_out;
  (void)in_sizes; (void)n_in; (void)out_size;

  cudaFuncSetAttribute(mma_gemm<false>, cudaFuncAttributeMaxDynamicSharedMemorySize, SMEM_BYTES);
  cudaFuncSetAttribute(mma_gemm<true>, cudaFuncAttributeMaxDynamicSharedMemorySize, SMEM_BYTES);

  __nv_bfloat16 *p_wq_hi, *p_wq_lo, *p_wo_hi, *p_wo_lo, *p_x_hi, *p_x_lo, *p_ao_hi, *p_ao_lo;
  cudaGetSymbolAddress((void**)&p_wq_hi, g_wq_hi);
  cudaGetSymbolAddress((void**)&p_wq_lo, g_wq_lo);
  cudaGetSymbolAddress((void**)&p_wo_hi, g_wo_hi);
  cudaGetSymbolAddress((void**)&p_wo_lo, g_wo_lo);
  cudaGetSymbolAddress((void**)&p_x_hi, g_x_hi);
  cudaGetSymbolAddress((void**)&p_x_lo, g_x_lo);
  cudaGetSymbolAddress((void**)&p_ao_hi, g_ao_hi);
  cudaGetSymbolAddress((void**)&p_ao_lo, g_ao_lo);

  split_kernel<<<(1536 * 512 / 4 + 255) / 256, 256>>>(w_qkv, p_wq_hi, p_wq_lo, 1536 * 512 / 4);
  split_kernel<<<(512 * 512 / 4 + 255) / 256, 256>>>(w_out, p_wo_hi, p_wo_lo, 512 * 512 / 4);
  ln_kernel<<<512, 128>>>(x, ln_g, ln_b);
  // A = weights (M rows), B = activations (N pix); m fastest keeps weights in L2
  mma_gemm<false><<<dim3(12, 512), 128, SMEM_BYTES>>>(p_wq_hi, p_wq_lo, p_x_hi, p_x_lo, nullptr, nullptr);
  attn_kernel<<<16384, 256>>>();
  mma_gemm<true><<<dim3(4, 512), 128, SMEM_BYTES>>>(p_wo_hi, p_wo_lo, p_ao_hi, p_ao_lo, b_out, out);
}